// round 2
// baseline (speedup 1.0000x reference)
#include <cuda_runtime.h>

// Global accumulators (zero-initialized at module load; reset by last block each call)
// [0]=sum(d^2), [1]=sum(d) over valid, [2..5]=bin sums s0..s3, [6..10]=bin counts c0..c4
__device__ double g_acc[11];
__device__ unsigned int g_ticket;

#define GRID 2048
#define TPB  256

struct Acc {
    float mse, sAll, s0, s1, s2, s3;
    unsigned long long pack;   // 5 x 12-bit count fields at bits 0,12,24,36,48; invalid -> bit 62
};

// ---- generic (exact) binning: idx = -1 + sum of predicates; strict > on q5
// implements the reference's (t == q5 -> bin 4) remap and the invalid >q5 case.
__device__ __forceinline__ void proc_generic(float p, float t,
                                             float q0, float q1, float q2,
                                             float q3, float q4, float q5,
                                             Acc& a) {
    float d = p - t;
    a.mse = fmaf(d, d, a.mse);
    int s6 = 0;
    s6 += (t >= q0); s6 += (t >= q1); s6 += (t >= q2);
    s6 += (t >= q3); s6 += (t >= q4); s6 += (t >  q5);
    int idx = s6 - 1;
    bool valid = ((unsigned)idx) <= 4u;
    float dv = valid ? d : 0.0f;
    a.sAll += dv;
    if (idx == 0) a.s0 += d;
    if (idx == 1) a.s1 += d;
    if (idx == 2) a.s2 += d;
    if (idx == 3) a.s3 += d;
    int sh = valid ? idx * 12 : 62;
    a.pack += 1ull << sh;
}

// ---- uniform-spacing fast path
__device__ __forceinline__ void proc_uniform(float p, float t,
                                             float q0, float inv_step, float q5,
                                             Acc& a) {
    float d = p - t;
    a.mse = fmaf(d, d, a.mse);
    float f = (t - q0) * inv_step;
    int idx = __float2int_rd(f);
    if (t == q5) idx = 4;          // closed last bin
    bool valid = ((unsigned)idx) <= 4u;
    float dv = valid ? d : 0.0f;
    a.sAll += dv;
    if (idx == 0) a.s0 += d;
    if (idx == 1) a.s1 += d;
    if (idx == 2) a.s2 += d;
    if (idx == 3) a.s3 += d;
    int sh = valid ? idx * 12 : 62;
    a.pack += 1ull << sh;
}

template <bool UNIFORM>
__device__ __forceinline__ void main_loop(const float4* __restrict__ p4,
                                          const float4* __restrict__ t4,
                                          const float* __restrict__ y_pred,
                                          const float* __restrict__ y_true,
                                          int n, int n4,
                                          float q0, float q1, float q2,
                                          float q3, float q4, float q5,
                                          float inv_step, Acc& a) {
    const int tid      = blockIdx.x * blockDim.x + threadIdx.x;
    const int nthreads = gridDim.x * blockDim.x;

#define PR(pp, tt)                                                     \
    do {                                                               \
        if (UNIFORM) proc_uniform((pp), (tt), q0, inv_step, q5, a);    \
        else proc_generic((pp), (tt), q0, q1, q2, q3, q4, q5, a);      \
    } while (0)

    int i = tid;
    // batched: 4 float4-pairs per iteration -> 8 front-loaded LDG.128 (MLP=8)
    for (; i + 3 * nthreads < n4; i += 4 * nthreads) {
        float4 pa = __ldcs(p4 + i);
        float4 pb = __ldcs(p4 + i + nthreads);
        float4 pc = __ldcs(p4 + i + 2 * nthreads);
        float4 pd = __ldcs(p4 + i + 3 * nthreads);
        float4 ta = __ldcs(t4 + i);
        float4 tb = __ldcs(t4 + i + nthreads);
        float4 tc = __ldcs(t4 + i + 2 * nthreads);
        float4 td = __ldcs(t4 + i + 3 * nthreads);
        PR(pa.x, ta.x); PR(pa.y, ta.y); PR(pa.z, ta.z); PR(pa.w, ta.w);
        PR(pb.x, tb.x); PR(pb.y, tb.y); PR(pb.z, tb.z); PR(pb.w, tb.w);
        PR(pc.x, tc.x); PR(pc.y, tc.y); PR(pc.z, tc.z); PR(pc.w, tc.w);
        PR(pd.x, td.x); PR(pd.y, td.y); PR(pd.z, td.z); PR(pd.w, td.w);
    }
    for (; i < n4; i += nthreads) {
        float4 pa = __ldcs(p4 + i);
        float4 ta = __ldcs(t4 + i);
        PR(pa.x, ta.x); PR(pa.y, ta.y); PR(pa.z, ta.z); PR(pa.w, ta.w);
    }
    for (int j = (n4 << 2) + tid; j < n; j += nthreads) {
        float p = y_pred[j];
        float t = y_true[j];
        PR(p, t);
    }
#undef PR
}

__global__ void __launch_bounds__(TPB)
fused_loss_kernel(const float* __restrict__ y_pred,
                  const float* __restrict__ y_true,
                  const float* __restrict__ quants,
                  float* __restrict__ out, int n) {
    const float q0 = __ldg(&quants[0]);
    const float q1 = __ldg(&quants[1]);
    const float q2 = __ldg(&quants[2]);
    const float q3 = __ldg(&quants[3]);
    const float q4 = __ldg(&quants[4]);
    const float q5 = __ldg(&quants[5]);

    // uniform-spacing detection (branch-coherent across the grid)
    const float step  = (q5 - q0) * 0.2f;
    const float span  = fmaxf(fabsf(q5), fabsf(q0)) + 1e-30f;
    const float eps   = 1e-5f * span;
    const bool uniform =
        step > 0.0f &&
        fabsf(q1 - (q0 + 1.0f * step)) <= eps &&
        fabsf(q2 - (q0 + 2.0f * step)) <= eps &&
        fabsf(q3 - (q0 + 3.0f * step)) <= eps &&
        fabsf(q4 - (q0 + 4.0f * step)) <= eps;
    const float inv_step = uniform ? (5.0f / (q5 - q0)) : 1.0f;

    Acc a = {0.0f, 0.0f, 0.0f, 0.0f, 0.0f, 0.0f, 0ull};

    const int n4 = n >> 2;
    const float4* __restrict__ p4 = (const float4*)y_pred;
    const float4* __restrict__ t4 = (const float4*)y_true;

    if (uniform)
        main_loop<true >(p4, t4, y_pred, y_true, n, n4, q0, q1, q2, q3, q4, q5, inv_step, a);
    else
        main_loop<false>(p4, t4, y_pred, y_true, n, n4, q0, q1, q2, q3, q4, q5, inv_step, a);

    // unpack counts once per thread
    float v[11];
    v[0] = a.mse; v[1] = a.sAll;
    v[2] = a.s0;  v[3] = a.s1;  v[4] = a.s2;  v[5] = a.s3;
#pragma unroll
    for (int j = 0; j < 5; j++)
        v[6 + j] = (float)((unsigned int)((a.pack >> (12 * j)) & 0xFFFull));

    // warp reduce
#pragma unroll
    for (int k = 0; k < 11; k++) {
#pragma unroll
        for (int off = 16; off > 0; off >>= 1)
            v[k] += __shfl_down_sync(0xFFFFFFFFu, v[k], off);
    }

    __shared__ float sh[TPB / 32][11];
    const int wid = threadIdx.x >> 5;
    const int lid = threadIdx.x & 31;
    if (lid == 0) {
#pragma unroll
        for (int k = 0; k < 11; k++) sh[wid][k] = v[k];
    }
    __syncthreads();

    if (threadIdx.x < 11) {
        float acc = 0.0f;
#pragma unroll
        for (int w = 0; w < TPB / 32; w++) acc += sh[w][threadIdx.x];
        atomicAdd(&g_acc[threadIdx.x], (double)acc);
    }
    __syncthreads();

    // last block finalizes and resets state for the next graph replay
    if (threadIdx.x == 0) {
        __threadfence();
        unsigned int ticket = atomicAdd(&g_ticket, 1u);
        if (ticket == gridDim.x - 1) {
            double A[11];
#pragma unroll
            for (int k = 0; k < 11; k++) A[k] = atomicAdd(&g_acc[k], 0.0);

            double mse = A[0] / (double)n;
            double s4 = A[1] - A[2] - A[3] - A[4] - A[5];
            double sums[5]   = {A[2], A[3], A[4], A[5], s4};
            double counts[5] = {A[6], A[7], A[8], A[9], A[10]};
            double m = 0.0;
#pragma unroll
            for (int j = 0; j < 5; j++) {
                double b  = sums[j] / fmax(counts[j], 1.0);
                double b2 = (counts[j] > 0.0) ? b * b : 0.0;
                m = fmax(m, b2);
            }
            m = fmax(m, 0.0);
            out[0] = (float)(mse + 5.0 * m);

            // reset for next call (kernel-exit flush makes this visible)
#pragma unroll
            for (int k = 0; k < 11; k++) g_acc[k] = 0.0;
            __threadfence();
            g_ticket = 0u;
        }
    }
}

extern "C" void kernel_launch(void* const* d_in, const int* in_sizes, int n_in,
                              void* d_out, int out_size) {
    const float* y_pred = (const float*)d_in[0];
    const float* y_true = (const float*)d_in[1];
    const float* quants = (const float*)d_in[2];
    float* out = (float*)d_out;
    const int n = in_sizes[0];

    fused_loss_kernel<<<GRID, TPB>>>(y_pred, y_true, quants, out, n);
}

// round 3
// speedup vs baseline: 2.5662x; 2.5662x over previous
#include <cuda_runtime.h>

// [0]=sum(d^2), [1..5]=bin sums s0..s4, [6..10]=bin counts c0..c4
__device__ double g_acc[11];
__device__ unsigned int g_ticket;

#define GRID 740     // 148 SMs x 5 resident blocks -> exactly one wave
#define TPB  256

__global__ void __launch_bounds__(TPB, 5)
fused_loss_kernel(const float* __restrict__ y_pred,
                  const float* __restrict__ y_true,
                  const float* __restrict__ quants,
                  float* __restrict__ out, int n)
{
    const float q0 = quants[0], q1 = quants[1], q2 = quants[2];
    const float q3 = quants[3], q4 = quants[4], q5 = quants[5];

    float mse = 0.0f;
    float s0 = 0, s1 = 0, s2 = 0, s3 = 0, s4 = 0;
    float c0 = 0, c1 = 0, c2 = 0, c3 = 0, c4 = 0;

    const int stride = GRID * TPB;
    const int tid    = blockIdx.x * TPB + threadIdx.x;
    const int n4     = n >> 2;
    const float4* __restrict__ p4 = (const float4*)y_pred;
    const float4* __restrict__ t4 = (const float4*)y_true;

// Interval binning == searchsorted(side='right')-1 with closed last bin:
// bin k (k<4): [qk, qk+1); bin 4: [q4, q5]. Out of range -> no bin (invalid).
#define PR(p_, t_)                                   \
    do {                                             \
        float t = (t_);                              \
        float d = (p_)-t;                            \
        mse = fmaf(d, d, mse);                       \
        bool b0 = (t >= q0) & (t < q1);              \
        bool b1 = (t >= q1) & (t < q2);              \
        bool b2 = (t >= q2) & (t < q3);              \
        bool b3 = (t >= q3) & (t < q4);              \
        bool b4 = (t >= q4) & (t <= q5);             \
        if (b0) { s0 += d; c0 += 1.0f; }             \
        if (b1) { s1 += d; c1 += 1.0f; }             \
        if (b2) { s2 += d; c2 += 1.0f; }             \
        if (b3) { s3 += d; c3 += 1.0f; }             \
        if (b4) { s4 += d; c4 += 1.0f; }             \
    } while (0)

    int i = tid;
    // two float4-pairs per iteration: 4 front-loaded LDG.128 (MLP=4)
    for (; i + stride < n4; i += 2 * stride) {
        float4 pa = p4[i];
        float4 pb = p4[i + stride];
        float4 ta = t4[i];
        float4 tb = t4[i + stride];
        PR(pa.x, ta.x); PR(pa.y, ta.y); PR(pa.z, ta.z); PR(pa.w, ta.w);
        PR(pb.x, tb.x); PR(pb.y, tb.y); PR(pb.z, tb.z); PR(pb.w, tb.w);
    }
    for (; i < n4; i += stride) {
        float4 pa = p4[i];
        float4 ta = t4[i];
        PR(pa.x, ta.x); PR(pa.y, ta.y); PR(pa.z, ta.z); PR(pa.w, ta.w);
    }
    for (int j = (n4 << 2) + tid; j < n; j += stride) {
        float p = y_pred[j];
        float t = y_true[j];
        PR(p, t);
    }
#undef PR

    // ---- block reduction of 11 partials ----
    float v[11] = {mse, s0, s1, s2, s3, s4, c0, c1, c2, c3, c4};
#pragma unroll
    for (int k = 0; k < 11; k++) {
#pragma unroll
        for (int off = 16; off > 0; off >>= 1)
            v[k] += __shfl_down_sync(0xFFFFFFFFu, v[k], off);
    }

    __shared__ float sh[TPB / 32][11];
    const int wid = threadIdx.x >> 5;
    const int lid = threadIdx.x & 31;
    if (lid == 0) {
#pragma unroll
        for (int k = 0; k < 11; k++) sh[wid][k] = v[k];
    }
    __syncthreads();

    if (threadIdx.x < 11) {
        float acc = 0.0f;
#pragma unroll
        for (int w = 0; w < TPB / 32; w++) acc += sh[w][threadIdx.x];
        atomicAdd(&g_acc[threadIdx.x], (double)acc);
    }

    // ---- last block finalizes and resets (graph-replay safe) ----
    __syncthreads();
    if (threadIdx.x == 0) {
        __threadfence();
        unsigned int ticket = atomicAdd(&g_ticket, 1u);
        if (ticket == GRID - 1) {
            double A[11];
#pragma unroll
            for (int k = 0; k < 11; k++) A[k] = atomicAdd(&g_acc[k], 0.0);

            double mse_d = A[0] / (double)n;
            double m = 0.0;
#pragma unroll
            for (int j = 0; j < 5; j++) {
                double s = A[1 + j];
                double c = A[6 + j];
                double b = s / fmax(c, 1.0);
                double b2 = (c > 0.0) ? b * b : 0.0;
                m = fmax(m, b2);
            }
            m = fmax(m, 0.0);
            out[0] = (float)(mse_d + 5.0 * m);

#pragma unroll
            for (int k = 0; k < 11; k++) g_acc[k] = 0.0;
            __threadfence();
            g_ticket = 0u;
        }
    }
}

extern "C" void kernel_launch(void* const* d_in, const int* in_sizes, int n_in,
                              void* d_out, int out_size) {
    const float* y_pred = (const float*)d_in[0];
    const float* y_true = (const float*)d_in[1];
    const float* quants = (const float*)d_in[2];
    float* out = (float*)d_out;
    const int n = in_sizes[0];

    fused_loss_kernel<<<GRID, TPB>>>(y_pred, y_true, quants, out, n);
}